// round 16
// baseline (speedup 1.0000x reference)
#include <cuda_runtime.h>
#include <cuda_bf16.h>

// Problem constants
#define B 64
#define L 512
#define T 8
#define D 1024
#define C 3
#define N_HOPS 6
#define LS 8
#define LCHUNK 64
#define NATTN (B * LS)
#define MVB 256            // matvec blocks per step

// ---------------- device scratch ----------------
__device__ float g_P[7][4][D];          // projection chains: [k][0]=W^k wa2, [k][1+m]=W^k Wout[:,m]
__device__ float g_c[5][B][L];          // c_k[b,l] = p_k . emb_row
__device__ float g_smb[B][L];           // v_loc * (emb . wa1)
__device__ float g_vloc[B][L];
__device__ float g_vec[B][D];           // v_aspect (vec_0)
__device__ float g_aw6[N_HOPS][B][L];   // alpha*v_loc per hop
__device__ float g_cp[LS][B][6][D];     // phase-C split-L partials

__device__ __forceinline__ float dot4(const float4 a, const float4 b) {
    return a.x * b.x + a.y * b.y + a.z * b.z + a.w * b.w;
}

__device__ __forceinline__ void ffma2(unsigned long long& d, unsigned long long a,
                                      unsigned long long b) {
    asm("fma.rn.f32x2 %0, %1, %2, %0;" : "+l"(d) : "l"(a), "l"(b));
}

union F4U2 {
    float4 f;
    unsigned long long u[2];
};

// ---------------- reduction helper (512-thread blocks) ---------------------------
template <int NV>
__device__ __forceinline__ void block_multired(float* v, float* scratch /*16*NV*/,
                                               float* out /*NV*/, int tid) {
    int lane = tid & 31, wid = tid >> 5;
    #pragma unroll
    for (int i = 0; i < NV; i++)
        #pragma unroll
        for (int o = 16; o > 0; o >>= 1)
            v[i] += __shfl_xor_sync(0xffffffffu, v[i], o);
    if (lane == 0)
        #pragma unroll
        for (int i = 0; i < NV; i++) scratch[wid * NV + i] = v[i];
    __syncthreads();
    if (tid < NV) {
        float s = 0.f;
        #pragma unroll
        for (int w = 0; w < 16; w++) s += scratch[w * NV + tid];
        out[tid] = s;
    }
    __syncthreads();
}

// ---------------- matvec step body (4 rows/block) --------------------------------
__device__ __forceinline__ void matvec_role(const float* __restrict__ W, int k,
                                            int vbid, int tid, float (*scr)[4]) {
    int r = tid >> 6;
    int i = tid & 63;
    int row = vbid * 4 + r;
    const float4* wrow = (const float4*)(W + (long)row * D);

    float4 w0 = wrow[i];
    float4 w1 = wrow[i + 64];
    float4 w2 = wrow[i + 128];
    float4 w3 = wrow[i + 192];

    float acc[4];
    #pragma unroll
    for (int c = 0; c < 4; c++) {
        const float4* p4 = (const float4*)g_P[k][c];
        acc[c] = dot4(w0, p4[i]) + dot4(w1, p4[i + 64])
               + dot4(w2, p4[i + 128]) + dot4(w3, p4[i + 192]);
    }

    #pragma unroll
    for (int c = 0; c < 4; c++)
        #pragma unroll
        for (int o = 16; o > 0; o >>= 1)
            acc[c] += __shfl_xor_sync(0xffffffffu, acc[c], o);

    int lane = tid & 31, warp = tid >> 5;
    if (lane == 0)
        #pragma unroll
        for (int c = 0; c < 4; c++) scr[warp][c] = acc[c];
    __syncthreads();

    if (tid < 16) {
        int rr = tid >> 2, c = tid & 3;
        g_P[k + 1][c][vbid * 4 + rr] = scr[2 * rr][c] + scr[2 * rr + 1][c];
    }
}

// ---------------- kernel: FUSED chain step k=0 (raw inputs) + proj_init ----------
// grid MVB+4. bid<MVB: matvec k=0 reading wattn/Wout directly -> g_P[1].
// bid>=MVB (4 blocks): write g_P[0] for downstream consumers.
__global__ void __launch_bounds__(256) mv0_f_k(const float* __restrict__ W,
                                               const float* __restrict__ wattn,
                                               const float* __restrict__ Wout) {
    __shared__ float scr[8][4];
    int tid = threadIdx.x;
    int bid = blockIdx.x;

    if (bid >= MVB) {
        int d = (bid - MVB) * 256 + tid;
        g_P[0][0][d] = wattn[D + d];
        #pragma unroll
        for (int m = 0; m < C; m++) g_P[0][1 + m][d] = Wout[d * C + m];
        return;
    }

    int r = tid >> 6;
    int i = tid & 63;
    int row = bid * 4 + r;
    const float4* wrow = (const float4*)(W + (long)row * D);

    float4 w[4];
    w[0] = wrow[i];
    w[1] = wrow[i + 64];
    w[2] = wrow[i + 128];
    w[3] = wrow[i + 192];

    float acc[4] = {};
    const float4* wa2 = (const float4*)(wattn + D);
    #pragma unroll
    for (int s = 0; s < 4; s++) {
        int idx = i + s * 64;            // float4 index
        acc[0] += dot4(w[s], wa2[idx]);
        int d0 = idx * 4;
        #pragma unroll
        for (int m = 0; m < C; m++) {
            float4 p;
            p.x = Wout[(d0 + 0) * C + m];
            p.y = Wout[(d0 + 1) * C + m];
            p.z = Wout[(d0 + 2) * C + m];
            p.w = Wout[(d0 + 3) * C + m];
            acc[1 + m] += dot4(w[s], p);
        }
    }

    #pragma unroll
    for (int c = 0; c < 4; c++)
        #pragma unroll
        for (int o = 16; o > 0; o >>= 1)
            acc[c] += __shfl_xor_sync(0xffffffffu, acc[c], o);

    int lane = tid & 31, warp = tid >> 5;
    if (lane == 0)
        #pragma unroll
        for (int c = 0; c < 4; c++) scr[warp][c] = acc[c];
    __syncthreads();

    if (tid < 16) {
        int rr = tid >> 2, c = tid & 3;
        g_P[1][c][bid * 4 + rr] = scr[2 * rr][c] + scr[2 * rr + 1][c];
    }
}

// ---------------- kernel: standalone chain step (k=1..3) -------------------------
__global__ void __launch_bounds__(256) matvec4_k(const float* __restrict__ W, int k) {
    __shared__ float scr[8][4];
    matvec_role(W, k, blockIdx.x, threadIdx.x, scr);
}

// ---------------- kernel: FUSED vaspect + chain step k=4 -------------------------
__global__ void __launch_bounds__(256) vaspect_f_k(const int* __restrict__ tgt,
                                                   const int* __restrict__ tlen,
                                                   const float* __restrict__ emb,
                                                   const float* __restrict__ W) {
    __shared__ float scr[8][4];
    int bid = blockIdx.x;
    int t = threadIdx.x;
    if (bid < MVB) {
        matvec_role(W, 4, bid, t, scr);
        return;
    }
    int b = bid - MVB;
    int n = tlen[b];
    float4 acc = make_float4(0.f, 0.f, 0.f, 0.f);
    #pragma unroll
    for (int i = 0; i < T; i++) {
        if (i < n) {
            int id = tgt[b * T + i];
            float4 e = ((const float4*)(emb + (long)id * D))[t];
            acc.x += e.x; acc.y += e.y; acc.z += e.z; acc.w += e.w;
        }
    }
    float inv = 1.0f / (float)n;
    acc.x *= inv; acc.y *= inv; acc.z *= inv; acc.w *= inv;
    ((float4*)g_vec[b])[t] = acc;
}

// ---------------- kernel: FUSED pass A + chain step k=5 --------------------------
__global__ void __launch_bounds__(256) preA_f_k(const int* __restrict__ ctx,
                                                const int* __restrict__ clen,
                                                const int* __restrict__ toff,
                                                const float* __restrict__ emb,
                                                const float* __restrict__ wattn,
                                                const float* __restrict__ W) {
    __shared__ float4 sp4[6 * 256];   // 24 KB; matvec role reuses the front as scr
    int tid = threadIdx.x;
    int bid = blockIdx.x;

    if (bid < MVB) {
        matvec_role(W, 5, bid, tid, (float(*)[4])sp4);
        return;
    }
    int idx = bid - MVB;
    int b = idx & 63;
    int ly = idx >> 6;

    #pragma unroll
    for (int i = tid; i < 6 * 256; i += 256) {
        int k = i >> 8, pos = i & 255;
        const float4* src = (k == 0) ? (const float4*)wattn
                                     : (const float4*)g_P[k - 1][0];
        sp4[i] = src[pos];
    }
    __syncthreads();

    int lane = tid & 31, warp = tid >> 5;
    int len = clen[b];
    int tofs = toff[b];
    int lbase = ly * 32 + warp * 4;

    const float4* erow[4];
    bool valid[4];
    #pragma unroll
    for (int r = 0; r < 4; r++) {
        int l = lbase + r;
        valid[r] = (l < len);
        erow[r] = (const float4*)(emb + (long)ctx[b * L + l] * D);
    }

    unsigned long long acc2[6][4] = {};
    const float4 z4 = make_float4(0.f, 0.f, 0.f, 0.f);

    #pragma unroll
    for (int i = 0; i < 8; i++) {
        F4U2 e[4];
        #pragma unroll
        for (int r = 0; r < 4; r++)
            e[r].f = valid[r] ? erow[r][i * 32 + lane] : z4;
        #pragma unroll
        for (int k = 0; k < 6; k++) {
            F4U2 p;
            p.f = sp4[k * 256 + i * 32 + lane];
            #pragma unroll
            for (int r = 0; r < 4; r++) {
                ffma2(acc2[k][r], p.u[0], e[r].u[0]);
                ffma2(acc2[k][r], p.u[1], e[r].u[1]);
            }
        }
    }

    float s[6][4];
    #pragma unroll
    for (int k = 0; k < 6; k++)
        #pragma unroll
        for (int r = 0; r < 4; r++) {
            float2 t2 = *(float2*)&acc2[k][r];
            float v = t2.x + t2.y;
            #pragma unroll
            for (int o = 16; o > 0; o >>= 1)
                v += __shfl_xor_sync(0xffffffffu, v, o);
            s[k][r] = v;
        }

    if (lane == 0) {
        #pragma unroll
        for (int r = 0; r < 4; r++) {
            int l = lbase + r;
            float v = valid[r]
                        ? 1.0f - fabsf((float)(l - tofs)) / (float)len
                        : 0.f;
            g_vloc[b][l] = v;
            g_smb[b][l] = v * s[0][r];
            g_c[0][b][l] = s[1][r];
            g_c[1][b][l] = s[2][r];
            g_c[2][b][l] = s[3][r];
            g_c[3][b][l] = s[4][r];
            g_c[4][b][l] = s[5][r];
        }
    }
}

// ---------------- kernel: scalar hop recurrence (no max reduce) -------------------
__global__ void scalar_k(const int* __restrict__ clen,
                         const float* __restrict__ blin,
                         const float* __restrict__ battn) {
    int b = blockIdx.x, t = threadIdx.x;
    __shared__ float scr[16 * 12];
    __shared__ float res12[12];
    __shared__ float t_arr[6];
    __shared__ float beta[6];

    {
        float vals[12];
        int d = t * 2;
        float2 v0 = *(const float2*)&g_vec[b][d];
        float2 bl = *(const float2*)&blin[d];
        #pragma unroll
        for (int k = 0; k < 6; k++) {
            float2 p = *(const float2*)&g_P[k][0][d];
            vals[k] = p.x * v0.x + p.y * v0.y;
            vals[6 + k] = p.x * bl.x + p.y * bl.y;
        }
        block_multired<12>(vals, scr, res12, t);
        if (t < 6) { t_arr[t] = res12[t]; beta[t] = res12[6 + t]; }
        __syncthreads();
    }

    int len = clen[b];
    bool valid = t < len;
    float smb_l = g_smb[b][t];
    float vloc_l = g_vloc[b][t];
    float cv[5];
    #pragma unroll
    for (int k = 0; k < 5; k++) cv[k] = g_c[k][b][t];
    float bat = battn[0];

    for (int h = 0; h < N_HOPS; h++) {
        float s = t_arr[0];
        float e = valid ? expf(tanhf(smb_l + s + bat)) : 0.f;
        float ev = e * vloc_l;

        float vals[6];
        vals[0] = e;
        #pragma unroll
        for (int k = 0; k < 5; k++) vals[1 + k] = ev * cv[k];
        block_multired<6>(vals, scr, res12, t);

        float inv_se = 1.0f / res12[0];
        g_aw6[h][b][t] = ev * inv_se;

        if (t == 0) {
            #pragma unroll
            for (int k = 0; k < 5; k++)       // ascending: reads t_arr[k+1] pre-update
                t_arr[k] = res12[1 + k] * inv_se + t_arr[k + 1] + beta[k];
        }
        __syncthreads();
    }
}

// ---------------- kernel: pass C — 6-way weighted sums (split L) -----------------
__global__ void phaseC_k(const int* __restrict__ ctx,
                         const int* __restrict__ clen,
                         const float* __restrict__ emb) {
    int bid = blockIdx.x;
    int b = bid & (B - 1);
    int ls = bid >> 6;
    int tid = threadIdx.x;
    __shared__ int ids[LCHUNK];
    __shared__ float w[6][LCHUNK];

    int l0 = ls * LCHUNK;
    if (tid < LCHUNK) ids[tid] = ctx[b * L + l0 + tid];
    for (int i = tid; i < 6 * LCHUNK; i += 256) {
        int j = i >> 6, li = i & (LCHUNK - 1);
        w[j][li] = g_aw6[j][b][l0 + li];
    }
    __syncthreads();

    int len = clen[b];
    int lend = len - l0;
    if (lend > LCHUNK) lend = LCHUNK;
    if (lend < 0) lend = 0;

    float4 acc[6] = {};
    const float4* e4 = (const float4*)emb;
    #pragma unroll 4
    for (int i = 0; i < lend; i++) {
        float4 ev = e4[(long)ids[i] * 256 + tid];
        #pragma unroll
        for (int j = 0; j < 6; j++) {
            float wj = w[j][i];
            acc[j].x += wj * ev.x;
            acc[j].y += wj * ev.y;
            acc[j].z += wj * ev.z;
            acc[j].w += wj * ev.w;
        }
    }
    #pragma unroll
    for (int j = 0; j < 6; j++)
        *(float4*)&g_cp[ls][b][j][tid * 4] = acc[j];
}

// ---------------- kernel: final logits (combine fused) ---------------------------
// grid B, 512 threads (float2 per thread). a_j[b][d] summed inline from g_cp.
__global__ void logits_f_k(const float* __restrict__ blin,
                           const float* __restrict__ bout,
                           float* __restrict__ out) {
    int b = blockIdx.x, t = threadIdx.x;
    __shared__ float scr[16 * 3];
    __shared__ float res[3];

    int d = t * 2;
    float2 v0 = *(const float2*)&g_vec[b][d];
    float2 bl = *(const float2*)&blin[d];

    // inline combine: a_j[d] = sum_ls cp[ls][b][j][d]
    float2 a[6];
    #pragma unroll
    for (int j = 0; j < 6; j++) a[j] = make_float2(0.f, 0.f);
    #pragma unroll
    for (int ls = 0; ls < LS; ls++) {
        #pragma unroll
        for (int j = 0; j < 6; j++) {
            float2 p = *(const float2*)&g_cp[ls][b][j][d];
            a[j].x += p.x;
            a[j].y += p.y;
        }
    }

    float pm[3] = {};
    #pragma unroll
    for (int m = 0; m < C; m++) {
        #pragma unroll
        for (int j = 0; j < 6; j++) {
            float2 u = *(const float2*)&g_P[5 - j][1 + m][d];
            pm[m] += u.x * a[j].x + u.y * a[j].y;
        }
        float2 u6 = *(const float2*)&g_P[6][1 + m][d];
        pm[m] += u6.x * v0.x + u6.y * v0.y;
        #pragma unroll
        for (int k = 0; k < 6; k++) {
            float2 uk = *(const float2*)&g_P[k][1 + m][d];
            pm[m] += uk.x * bl.x + uk.y * bl.y;
        }
    }
    block_multired<3>(pm, scr, res, t);
    if (t < C) out[b * C + t] = res[t] + bout[t];
}

// ---------------- launcher -------------------------------------------------------
extern "C" void kernel_launch(void* const* d_in, const int* in_sizes, int n_in,
                              void* d_out, int out_size) {
    const int*   ctx   = (const int*)d_in[0];
    const int*   tgt   = (const int*)d_in[1];
    const int*   clen  = (const int*)d_in[2];
    const int*   tlen  = (const int*)d_in[3];
    const int*   toff  = (const int*)d_in[4];
    const float* emb   = (const float*)d_in[5];
    const float* Wlin  = (const float*)d_in[6];
    const float* blin  = (const float*)d_in[7];
    const float* wattn = (const float*)d_in[8];
    const float* battn = (const float*)d_in[9];
    const float* Wout  = (const float*)d_in[10];
    const float* bout  = (const float*)d_in[11];
    float* out = (float*)d_out;

    mv0_f_k<<<MVB + 4, 256>>>(Wlin, wattn, Wout);                 // chain k=0 + init
    for (int k = 1; k < 4; k++)
        matvec4_k<<<MVB, 256>>>(Wlin, k);
    vaspect_f_k<<<MVB + B, 256>>>(tgt, tlen, emb, Wlin);          // + chain k=4
    preA_f_k<<<MVB + B * 16, 256>>>(ctx, clen, toff, emb, wattn, Wlin); // + chain k=5
    scalar_k<<<B, 512>>>(clen, blin, battn);
    phaseC_k<<<NATTN, 256>>>(ctx, clen, emb);
    logits_f_k<<<B, 512>>>(blin, bout, out);
}